// round 6
// baseline (speedup 1.0000x reference)
#include <cuda_runtime.h>
#include <cstdint>

#define SS 256
#define BB 16
#define EE 512
#define HH 1024
#define TT 64
#define G4 4096
#define NSLOT 4096
#define DIN0 576

// ---------------- device scratch (static; no runtime allocation) ----------
__device__ float g_Xg[2][NSLOT][G4];        // layer0 gate x-part (+bih0+bhh0)
__device__ float g_a1[2][NSLOT][G4];        // layer1 gate input part (+biases)
__device__ float g_h0[2][NSLOT][HH];
__device__ float g_h1[2][NSLOT][HH];
__device__ float g_tagbuf[2][NSLOT + 16][TT];  // +16 rows of zeros at front
__device__ int   g_fH0[2][NSLOT];
__device__ int   g_fA1[2][NSLOT];
__device__ int   g_fH1[2][NSLOT];
__device__ int   g_fTAG[2][NSLOT];

// ---------------- helpers --------------------------------------------------
__device__ __forceinline__ int ld_acq(const int* p) {
    int v;
    asm volatile("ld.acquire.gpu.global.b32 %0, [%1];" : "=r"(v) : "l"(p));
    return v;
}
__device__ __forceinline__ void wait_ge(const int* p, int v) {
    while (ld_acq(p) < v) { __nanosleep(32); }
}
__device__ __forceinline__ float sigf(float x) { return 1.0f / (1.0f + expf(-x)); }
__device__ __forceinline__ float wredsum(float v) {
#pragma unroll
    for (int off = 16; off; off >>= 1) v += __shfl_xor_sync(0xffffffffu, v, off);
    return v;
}

// ---------------- flag / zero-init (graph-replay safe) ---------------------
__global__ void zero_flags() {
    int i = blockIdx.x * blockDim.x + threadIdx.x;
    if (i < 2 * NSLOT) {
        ((int*)g_fH0)[i] = 0;
        ((int*)g_fA1)[i] = 0;
        ((int*)g_fH1)[i] = 0;
        ((int*)g_fTAG)[i] = 0;
    }
    if (i < 2 * 16 * TT) {
        int d = i / (16 * TT);
        int r = i % (16 * TT);
        g_tagbuf[d][r / TT][r % TT] = 0.0f;
    }
}

// ---------------- Xg GEMM: (4096 slots) x (4096 rows) x (512) --------------
__global__ void __launch_bounds__(256) xg_gemm(
    const float* __restrict__ x,
    const float* __restrict__ Wf, const float* __restrict__ bihf, const float* __restrict__ bhhf,
    const float* __restrict__ Wb, const float* __restrict__ bihb, const float* __restrict__ bhhb) {
    int dir = blockIdx.z;
    const float* W   = dir ? Wb   : Wf;
    const float* bih = dir ? bihb : bihf;
    const float* bhh = dir ? bhhb : bhhf;
    int n0 = blockIdx.x * 64;
    int m0 = blockIdx.y * 64;

    __shared__ __align__(16) float As[32][72];
    __shared__ __align__(16) float Bs[32][72];

    int tid = threadIdx.x;
    int tm = tid >> 4, tn = tid & 15;
    float acc[4][4] = {};

    int th_row = tid >> 2;
    int th_c = (tid & 3) * 8;

    int mslot = m0 + th_row;
    int tt = mslot >> 4, bb = mslot & 15;
    int tsrc = dir ? (SS - 1 - tt) : tt;
    const float* arow = x + ((size_t)bb * SS + tsrc) * EE;
    const float* brow = W + (size_t)(n0 + th_row) * DIN0;

    for (int k0 = 0; k0 < EE; k0 += 32) {
#pragma unroll
        for (int u = 0; u < 8; ++u) {
            As[th_c + u][th_row] = arow[k0 + th_c + u];
            Bs[th_c + u][th_row] = brow[k0 + th_c + u];
        }
        __syncthreads();
#pragma unroll
        for (int kk = 0; kk < 32; ++kk) {
            float av[4], bv[4];
            *(float4*)av = *(const float4*)&As[kk][tm * 4];
            *(float4*)bv = *(const float4*)&Bs[kk][tn * 4];
#pragma unroll
            for (int ii = 0; ii < 4; ++ii)
#pragma unroll
                for (int jj = 0; jj < 4; ++jj) acc[ii][jj] += av[ii] * bv[jj];
        }
        __syncthreads();
    }
#pragma unroll
    for (int ii = 0; ii < 4; ++ii) {
        int m = m0 + tm * 4 + ii;
#pragma unroll
        for (int jj = 0; jj < 4; ++jj) {
            int n = n0 + tn * 4 + jj;
            g_Xg[dir][m][n] = acc[ii][jj] + bih[n] + bhh[n];
        }
    }
}

// ---------------- persistent pipelined sequential kernel -------------------
// 98 blocks: per dir 49: [0..15] E0, [16..31] E1A, [32..47] E1B, [48] TAG.
__global__ void __launch_bounds__(512, 1) lstm_seq(
    const float* __restrict__ fWih0, const float* __restrict__ fWhh0,
    const float* __restrict__ fWih1, const float* __restrict__ fWhh1,
    const float* __restrict__ fbih1, const float* __restrict__ fbhh1,
    const float* __restrict__ fWtag, const float* __restrict__ fbtag,
    const float* __restrict__ bWih0, const float* __restrict__ bWhh0,
    const float* __restrict__ bWih1, const float* __restrict__ bWhh1,
    const float* __restrict__ bbih1, const float* __restrict__ bbhh1,
    const float* __restrict__ bWtag, const float* __restrict__ bbtag) {
    int dir = blockIdx.x / 49;
    int role = blockIdx.x % 49;
    const float* Wih0 = dir ? bWih0 : fWih0;
    const float* Whh0 = dir ? bWhh0 : fWhh0;
    const float* Wih1 = dir ? bWih1 : fWih1;
    const float* Whh1 = dir ? bWhh1 : fWhh1;
    const float* bih1 = dir ? bbih1 : fbih1;
    const float* bhh1 = dir ? bbhh1 : fbhh1;
    const float* Wtag = dir ? bWtag : fWtag;
    const float* btag = dir ? bbtag : fbtag;

    int tid = threadIdx.x;
    int w = tid >> 5, lane = tid & 31;

    __shared__ __align__(16) float sh_h[HH];
    __shared__ float sh_tag[TT];
    __shared__ float sh_acc[16][16];
    __shared__ float c_sh[64];

    if (role < 16) {
        // ------- E0: layer-0 recurrence (Whh0 + prev-tag cols of Wih0) -----
        int hbase = role * 64;
        if (tid < 64) c_sh[tid] = 0.0f;
        for (int i = 0; i < NSLOT; ++i) {
            if (tid == 0) {
                if (i > 0) wait_ge(&g_fH0[dir][i - 1], 16);
                if (i >= 16) wait_ge(&g_fTAG[dir][i - 16], 1);
            }
            __syncthreads();
            if (i > 0) {
                for (int q = tid; q < HH; q += 512) sh_h[q] = g_h0[dir][i - 1][q];
            } else {
                for (int q = tid; q < HH; q += 512) sh_h[q] = 0.0f;
            }
            if (tid < 64) sh_tag[tid] = g_tagbuf[dir][i][tid];
            __syncthreads();

            float4 hv[8];
            const float4* shf = (const float4*)sh_h;
#pragma unroll
            for (int it = 0; it < 8; ++it) hv[it] = shf[lane + 32 * it];
            float tp0 = sh_tag[lane * 2], tp1 = sh_tag[lane * 2 + 1];

            for (int r = 0; r < 16; ++r) {
                int u = r >> 2, gsel = r & 3;
                int row = gsel * 1024 + hbase + w * 4 + u;
                const float4* wr = (const float4*)(Whh0 + (size_t)row * HH);
                float a = 0.0f;
#pragma unroll
                for (int it = 0; it < 8; ++it) {
                    float4 ww = wr[lane + 32 * it];
                    a += ww.x * hv[it].x + ww.y * hv[it].y + ww.z * hv[it].z + ww.w * hv[it].w;
                }
                float2 wp = *(const float2*)(Wih0 + (size_t)row * DIN0 + 512 + lane * 2);
                a += wp.x * tp0 + wp.y * tp1;
                a = wredsum(a);
                if (lane == 0) sh_acc[w][r] = a + g_Xg[dir][i][row];
            }
            __syncwarp();
            if (lane < 4) {
                int lj = w * 4 + lane;
                float gi = sh_acc[w][lane * 4 + 0];
                float gf = sh_acc[w][lane * 4 + 1];
                float gg = sh_acc[w][lane * 4 + 2];
                float go = sh_acc[w][lane * 4 + 3];
                float c = sigf(gf) * c_sh[lj] + sigf(gi) * tanhf(gg);
                float h = sigf(go) * tanhf(c);
                c_sh[lj] = c;
                g_h0[dir][i][hbase + lj] = h;
            }
            __syncthreads();
            if (tid == 0) { __threadfence(); atomicAdd(&g_fH0[dir][i], 1); }
        }
    } else if (role < 32) {
        // ------- E1A: a1 = Wih1 . h0 + biases ------------------------------
        int rbase = (role - 16) * 256;
        for (int i = 0; i < NSLOT; ++i) {
            if (tid == 0) wait_ge(&g_fH0[dir][i], 16);
            __syncthreads();
            for (int q = tid; q < HH; q += 512) sh_h[q] = g_h0[dir][i][q];
            __syncthreads();
            float4 hv[8];
            const float4* shf = (const float4*)sh_h;
#pragma unroll
            for (int it = 0; it < 8; ++it) hv[it] = shf[lane + 32 * it];
            for (int r = 0; r < 16; ++r) {
                int row = rbase + w * 16 + r;
                const float4* wr = (const float4*)(Wih1 + (size_t)row * HH);
                float a = 0.0f;
#pragma unroll
                for (int it = 0; it < 8; ++it) {
                    float4 ww = wr[lane + 32 * it];
                    a += ww.x * hv[it].x + ww.y * hv[it].y + ww.z * hv[it].z + ww.w * hv[it].w;
                }
                a = wredsum(a);
                if (lane == 0) g_a1[dir][i][row] = a + bih1[row] + bhh1[row];
            }
            __syncthreads();
            if (tid == 0) { __threadfence(); atomicAdd(&g_fA1[dir][i], 1); }
        }
    } else if (role < 48) {
        // ------- E1B: layer-1 recurrence (Whh1) ----------------------------
        int hbase = (role - 32) * 64;
        if (tid < 64) c_sh[tid] = 0.0f;
        for (int i = 0; i < NSLOT; ++i) {
            if (tid == 0) {
                wait_ge(&g_fA1[dir][i], 16);
                if (i > 0) wait_ge(&g_fH1[dir][i - 1], 16);
            }
            __syncthreads();
            if (i > 0) {
                for (int q = tid; q < HH; q += 512) sh_h[q] = g_h1[dir][i - 1][q];
            } else {
                for (int q = tid; q < HH; q += 512) sh_h[q] = 0.0f;
            }
            __syncthreads();
            float4 hv[8];
            const float4* shf = (const float4*)sh_h;
#pragma unroll
            for (int it = 0; it < 8; ++it) hv[it] = shf[lane + 32 * it];
            for (int r = 0; r < 16; ++r) {
                int u = r >> 2, gsel = r & 3;
                int row = gsel * 1024 + hbase + w * 4 + u;
                const float4* wr = (const float4*)(Whh1 + (size_t)row * HH);
                float a = 0.0f;
#pragma unroll
                for (int it = 0; it < 8; ++it) {
                    float4 ww = wr[lane + 32 * it];
                    a += ww.x * hv[it].x + ww.y * hv[it].y + ww.z * hv[it].z + ww.w * hv[it].w;
                }
                a = wredsum(a);
                if (lane == 0) sh_acc[w][r] = a + g_a1[dir][i][row];
            }
            __syncwarp();
            if (lane < 4) {
                int lj = w * 4 + lane;
                float gi = sh_acc[w][lane * 4 + 0];
                float gf = sh_acc[w][lane * 4 + 1];
                float gg = sh_acc[w][lane * 4 + 2];
                float go = sh_acc[w][lane * 4 + 3];
                float c = sigf(gf) * c_sh[lj] + sigf(gi) * tanhf(gg);
                float h = sigf(go) * tanhf(c);
                c_sh[lj] = c;
                g_h1[dir][i][hbase + lj] = h;
            }
            __syncthreads();
            if (tid == 0) { __threadfence(); atomicAdd(&g_fH1[dir][i], 1); }
        }
    } else {
        // ------- TAG: out = Wtag . h1 + btag -------------------------------
        for (int i = 0; i < NSLOT; ++i) {
            if (tid == 0) wait_ge(&g_fH1[dir][i], 16);
            __syncthreads();
            for (int q = tid; q < HH; q += 512) sh_h[q] = g_h1[dir][i][q];
            __syncthreads();
            float4 hv[8];
            const float4* shf = (const float4*)sh_h;
#pragma unroll
            for (int it = 0; it < 8; ++it) hv[it] = shf[lane + 32 * it];
            for (int r = 0; r < 4; ++r) {
                int row = w * 4 + r;
                const float4* wr = (const float4*)(Wtag + (size_t)row * HH);
                float a = 0.0f;
#pragma unroll
                for (int it = 0; it < 8; ++it) {
                    float4 ww = wr[lane + 32 * it];
                    a += ww.x * hv[it].x + ww.y * hv[it].y + ww.z * hv[it].z + ww.w * hv[it].w;
                }
                a = wredsum(a);
                if (lane == 0) g_tagbuf[dir][i + 16][row] = a + btag[row];
            }
            __syncthreads();
            if (tid == 0) { __threadfence(); atomicAdd(&g_fTAG[dir][i], 1); }
        }
    }
}

// ---------------- final add + log_softmax ----------------------------------
__global__ void finalize(float* __restrict__ out) {
    int blk = blockIdx.x;          // b*SS + s
    int b = blk / SS, s = blk % SS;
    int lane = threadIdx.x;        // 32 threads
    int sf = (s * 16 + b) + 16;
    int sb = ((SS - 1 - s) * 16 + b) + 16;
    float v0 = g_tagbuf[0][sf][lane] + g_tagbuf[1][sb][lane];
    float v1 = g_tagbuf[0][sf][lane + 32] + g_tagbuf[1][sb][lane + 32];
    float m = fmaxf(v0, v1);
#pragma unroll
    for (int off = 16; off; off >>= 1) m = fmaxf(m, __shfl_xor_sync(0xffffffffu, m, off));
    float e = expf(v0 - m) + expf(v1 - m);
#pragma unroll
    for (int off = 16; off; off >>= 1) e += __shfl_xor_sync(0xffffffffu, e, off);
    float ls = m + logf(e);
    out[((size_t)b * SS + s) * TT + lane] = v0 - ls;
    out[((size_t)b * SS + s) * TT + lane + 32] = v1 - ls;
}

// ---------------- launch ----------------------------------------------------
extern "C" void kernel_launch(void* const* d_in, const int* in_sizes, int n_in,
                              void* d_out, int out_size) {
    const float* x = (const float*)d_in[0];
    const float* fWih0 = (const float*)d_in[1];
    const float* fWhh0 = (const float*)d_in[2];
    const float* fbih0 = (const float*)d_in[3];
    const float* fbhh0 = (const float*)d_in[4];
    const float* fWih1 = (const float*)d_in[5];
    const float* fWhh1 = (const float*)d_in[6];
    const float* fbih1 = (const float*)d_in[7];
    const float* fbhh1 = (const float*)d_in[8];
    const float* fWtag = (const float*)d_in[9];
    const float* fbtag = (const float*)d_in[10];
    const float* bWih0 = (const float*)d_in[11];
    const float* bWhh0 = (const float*)d_in[12];
    const float* bbih0 = (const float*)d_in[13];
    const float* bbhh0 = (const float*)d_in[14];
    const float* bWih1 = (const float*)d_in[15];
    const float* bWhh1 = (const float*)d_in[16];
    const float* bbih1 = (const float*)d_in[17];
    const float* bbhh1 = (const float*)d_in[18];
    const float* bWtag = (const float*)d_in[19];
    const float* bbtag = (const float*)d_in[20];

    zero_flags<<<16, 512>>>();
    xg_gemm<<<dim3(G4 / 64, G4 / 64, 2), 256>>>(x, fWih0, fbih0, fbhh0, bWih0, bbih0, bbhh0);
    lstm_seq<<<98, 512>>>(fWih0, fWhh0, fWih1, fWhh1, fbih1, fbhh1, fWtag, fbtag,
                          bWih0, bWhh0, bWih1, bWhh1, bbih1, bbhh1, bWtag, bbtag);
    finalize<<<BB * SS, 32>>>((float*)d_out);
}

// round 7
// speedup vs baseline: 1.0019x; 1.0019x over previous
#include <cuda_runtime.h>
#include <cstdint>

#define SS 256
#define BB 16
#define EE 512
#define HH 1024
#define TT 64
#define G4 4096
#define NSLOT 4096
#define DIN0 576

// ---------------- device scratch (static; no runtime allocation) ----------
__device__ float g_Xg[2][NSLOT][G4];        // layer0 gate x-part (+bih0+bhh0)
__device__ float g_a1[2][NSLOT][G4];        // layer1 gate input part (+biases)
__device__ float g_h0[2][NSLOT][HH];
__device__ float g_h1[2][NSLOT][HH];
__device__ float g_tagbuf[2][NSLOT + 16][TT];  // +16 rows of zeros at front
__device__ int   g_fH0[2][NSLOT];
__device__ int   g_fA1[2][NSLOT];
__device__ int   g_fH1[2][NSLOT];
__device__ int   g_fTAG[2][NSLOT];

// ---------------- helpers --------------------------------------------------
__device__ __forceinline__ int ld_acq(const int* p) {
    int v;
    asm volatile("ld.acquire.gpu.global.b32 %0, [%1];" : "=r"(v) : "l"(p));
    return v;
}
__device__ __forceinline__ void wait_ge(const int* p, int v) {
    while (ld_acq(p) < v) { __nanosleep(32); }
}
__device__ __forceinline__ float sigf(float x) { return 1.0f / (1.0f + expf(-x)); }
__device__ __forceinline__ float wredsum(float v) {
#pragma unroll
    for (int off = 16; off; off >>= 1) v += __shfl_xor_sync(0xffffffffu, v, off);
    return v;
}

// ---------------- flag / zero-init (graph-replay safe) ---------------------
__global__ void zero_flags() {
    int i = blockIdx.x * blockDim.x + threadIdx.x;
    if (i < 2 * NSLOT) {
        ((int*)g_fH0)[i] = 0;
        ((int*)g_fA1)[i] = 0;
        ((int*)g_fH1)[i] = 0;
        ((int*)g_fTAG)[i] = 0;
    }
    if (i < 2 * 16 * TT) {
        int d = i / (16 * TT);
        int r = i % (16 * TT);
        g_tagbuf[d][r / TT][r % TT] = 0.0f;
    }
}

// ---------------- Xg GEMM: (4096 slots) x (4096 rows) x (512) --------------
__global__ void __launch_bounds__(256) xg_gemm(
    const float* __restrict__ x,
    const float* __restrict__ Wf, const float* __restrict__ bihf, const float* __restrict__ bhhf,
    const float* __restrict__ Wb, const float* __restrict__ bihb, const float* __restrict__ bhhb) {
    int dir = blockIdx.z;
    const float* W   = dir ? Wb   : Wf;
    const float* bih = dir ? bihb : bihf;
    const float* bhh = dir ? bhhb : bhhf;
    int n0 = blockIdx.x * 64;
    int m0 = blockIdx.y * 64;

    __shared__ __align__(16) float As[32][72];
    __shared__ __align__(16) float Bs[32][72];

    int tid = threadIdx.x;
    int tm = tid >> 4, tn = tid & 15;
    float acc[4][4] = {};

    int th_row = tid >> 2;
    int th_c = (tid & 3) * 8;

    int mslot = m0 + th_row;
    int tt = mslot >> 4, bb = mslot & 15;
    int tsrc = dir ? (SS - 1 - tt) : tt;
    const float* arow = x + ((size_t)bb * SS + tsrc) * EE;
    const float* brow = W + (size_t)(n0 + th_row) * DIN0;

    for (int k0 = 0; k0 < EE; k0 += 32) {
#pragma unroll
        for (int u = 0; u < 8; ++u) {
            As[th_c + u][th_row] = arow[k0 + th_c + u];
            Bs[th_c + u][th_row] = brow[k0 + th_c + u];
        }
        __syncthreads();
#pragma unroll
        for (int kk = 0; kk < 32; ++kk) {
            float av[4], bv[4];
            *(float4*)av = *(const float4*)&As[kk][tm * 4];
            *(float4*)bv = *(const float4*)&Bs[kk][tn * 4];
#pragma unroll
            for (int ii = 0; ii < 4; ++ii)
#pragma unroll
                for (int jj = 0; jj < 4; ++jj) acc[ii][jj] += av[ii] * bv[jj];
        }
        __syncthreads();
    }
#pragma unroll
    for (int ii = 0; ii < 4; ++ii) {
        int m = m0 + tm * 4 + ii;
#pragma unroll
        for (int jj = 0; jj < 4; ++jj) {
            int n = n0 + tn * 4 + jj;
            g_Xg[dir][m][n] = acc[ii][jj] + bih[n] + bhh[n];
        }
    }
}

// ---------------- persistent pipelined sequential kernel -------------------
// 98 blocks: per dir 49: [0..15] E0, [16..31] E1A, [32..47] E1B, [48] TAG.
__global__ void __launch_bounds__(512, 1) lstm_seq(
    const float* __restrict__ fWih0, const float* __restrict__ fWhh0,
    const float* __restrict__ fWih1, const float* __restrict__ fWhh1,
    const float* __restrict__ fbih1, const float* __restrict__ fbhh1,
    const float* __restrict__ fWtag, const float* __restrict__ fbtag,
    const float* __restrict__ bWih0, const float* __restrict__ bWhh0,
    const float* __restrict__ bWih1, const float* __restrict__ bWhh1,
    const float* __restrict__ bbih1, const float* __restrict__ bbhh1,
    const float* __restrict__ bWtag, const float* __restrict__ bbtag) {
    int dir = blockIdx.x / 49;
    int role = blockIdx.x % 49;
    const float* Wih0 = dir ? bWih0 : fWih0;
    const float* Whh0 = dir ? bWhh0 : fWhh0;
    const float* Wih1 = dir ? bWih1 : fWih1;
    const float* Whh1 = dir ? bWhh1 : fWhh1;
    const float* bih1 = dir ? bbih1 : fbih1;
    const float* bhh1 = dir ? bbhh1 : fbhh1;
    const float* Wtag = dir ? bWtag : fWtag;
    const float* btag = dir ? bbtag : fbtag;

    int tid = threadIdx.x;
    int w = tid >> 5, lane = tid & 31;

    __shared__ __align__(16) float sh_h[HH];
    __shared__ float sh_tag[TT];
    __shared__ float sh_acc[16][16];
    __shared__ float c_sh[64];

    if (role < 16) {
        // ------- E0: layer-0 recurrence (Whh0 + prev-tag cols of Wih0) -----
        int hbase = role * 64;
        if (tid < 64) c_sh[tid] = 0.0f;
        for (int i = 0; i < NSLOT; ++i) {
            if (tid == 0) {
                if (i > 0) wait_ge(&g_fH0[dir][i - 1], 16);
                if (i >= 16) wait_ge(&g_fTAG[dir][i - 16], 1);
            }
            __syncthreads();
            if (i > 0) {
                for (int q = tid; q < HH; q += 512) sh_h[q] = g_h0[dir][i - 1][q];
            } else {
                for (int q = tid; q < HH; q += 512) sh_h[q] = 0.0f;
            }
            if (tid < 64) sh_tag[tid] = g_tagbuf[dir][i][tid];
            __syncthreads();

            float4 hv[8];
            const float4* shf = (const float4*)sh_h;
#pragma unroll
            for (int it = 0; it < 8; ++it) hv[it] = shf[lane + 32 * it];
            float tp0 = sh_tag[lane * 2], tp1 = sh_tag[lane * 2 + 1];

            for (int r = 0; r < 16; ++r) {
                int u = r >> 2, gsel = r & 3;
                int row = gsel * 1024 + hbase + w * 4 + u;
                const float4* wr = (const float4*)(Whh0 + (size_t)row * HH);
                float a = 0.0f;
#pragma unroll
                for (int it = 0; it < 8; ++it) {
                    float4 ww = wr[lane + 32 * it];
                    a += ww.x * hv[it].x + ww.y * hv[it].y + ww.z * hv[it].z + ww.w * hv[it].w;
                }
                float2 wp = *(const float2*)(Wih0 + (size_t)row * DIN0 + 512 + lane * 2);
                a += wp.x * tp0 + wp.y * tp1;
                a = wredsum(a);
                if (lane == 0) sh_acc[w][r] = a + g_Xg[dir][i][row];
            }
            __syncwarp();
            if (lane < 4) {
                int lj = w * 4 + lane;
                float gi = sh_acc[w][lane * 4 + 0];
                float gf = sh_acc[w][lane * 4 + 1];
                float gg = sh_acc[w][lane * 4 + 2];
                float go = sh_acc[w][lane * 4 + 3];
                float c = sigf(gf) * c_sh[lj] + sigf(gi) * tanhf(gg);
                float h = sigf(go) * tanhf(c);
                c_sh[lj] = c;
                g_h0[dir][i][hbase + lj] = h;
            }
            __syncthreads();
            if (tid == 0) { __threadfence(); atomicAdd(&g_fH0[dir][i], 1); }
        }
    } else if (role < 32) {
        // ------- E1A: a1 = Wih1 . h0 + biases ------------------------------
        int rbase = (role - 16) * 256;
        for (int i = 0; i < NSLOT; ++i) {
            if (tid == 0) wait_ge(&g_fH0[dir][i], 16);
            __syncthreads();
            for (int q = tid; q < HH; q += 512) sh_h[q] = g_h0[dir][i][q];
            __syncthreads();
            float4 hv[8];
            const float4* shf = (const float4*)sh_h;
#pragma unroll
            for (int it = 0; it < 8; ++it) hv[it] = shf[lane + 32 * it];
            for (int r = 0; r < 16; ++r) {
                int row = rbase + w * 16 + r;
                const float4* wr = (const float4*)(Wih1 + (size_t)row * HH);
                float a = 0.0f;
#pragma unroll
                for (int it = 0; it < 8; ++it) {
                    float4 ww = wr[lane + 32 * it];
                    a += ww.x * hv[it].x + ww.y * hv[it].y + ww.z * hv[it].z + ww.w * hv[it].w;
                }
                a = wredsum(a);
                if (lane == 0) g_a1[dir][i][row] = a + bih1[row] + bhh1[row];
            }
            __syncthreads();
            if (tid == 0) { __threadfence(); atomicAdd(&g_fA1[dir][i], 1); }
        }
    } else if (role < 48) {
        // ------- E1B: layer-1 recurrence (Whh1) ----------------------------
        int hbase = (role - 32) * 64;
        if (tid < 64) c_sh[tid] = 0.0f;
        for (int i = 0; i < NSLOT; ++i) {
            if (tid == 0) {
                wait_ge(&g_fA1[dir][i], 16);
                if (i > 0) wait_ge(&g_fH1[dir][i - 1], 16);
            }
            __syncthreads();
            if (i > 0) {
                for (int q = tid; q < HH; q += 512) sh_h[q] = g_h1[dir][i - 1][q];
            } else {
                for (int q = tid; q < HH; q += 512) sh_h[q] = 0.0f;
            }
            __syncthreads();
            float4 hv[8];
            const float4* shf = (const float4*)sh_h;
#pragma unroll
            for (int it = 0; it < 8; ++it) hv[it] = shf[lane + 32 * it];
            for (int r = 0; r < 16; ++r) {
                int u = r >> 2, gsel = r & 3;
                int row = gsel * 1024 + hbase + w * 4 + u;
                const float4* wr = (const float4*)(Whh1 + (size_t)row * HH);
                float a = 0.0f;
#pragma unroll
                for (int it = 0; it < 8; ++it) {
                    float4 ww = wr[lane + 32 * it];
                    a += ww.x * hv[it].x + ww.y * hv[it].y + ww.z * hv[it].z + ww.w * hv[it].w;
                }
                a = wredsum(a);
                if (lane == 0) sh_acc[w][r] = a + g_a1[dir][i][row];
            }
            __syncwarp();
            if (lane < 4) {
                int lj = w * 4 + lane;
                float gi = sh_acc[w][lane * 4 + 0];
                float gf = sh_acc[w][lane * 4 + 1];
                float gg = sh_acc[w][lane * 4 + 2];
                float go = sh_acc[w][lane * 4 + 3];
                float c = sigf(gf) * c_sh[lj] + sigf(gi) * tanhf(gg);
                float h = sigf(go) * tanhf(c);
                c_sh[lj] = c;
                g_h1[dir][i][hbase + lj] = h;
            }
            __syncthreads();
            if (tid == 0) { __threadfence(); atomicAdd(&g_fH1[dir][i], 1); }
        }
    } else {
        // ------- TAG: out = Wtag . h1 + btag -------------------------------
        for (int i = 0; i < NSLOT; ++i) {
            if (tid == 0) wait_ge(&g_fH1[dir][i], 16);
            __syncthreads();
            for (int q = tid; q < HH; q += 512) sh_h[q] = g_h1[dir][i][q];
            __syncthreads();
            float4 hv[8];
            const float4* shf = (const float4*)sh_h;
#pragma unroll
            for (int it = 0; it < 8; ++it) hv[it] = shf[lane + 32 * it];
            for (int r = 0; r < 4; ++r) {
                int row = w * 4 + r;
                const float4* wr = (const float4*)(Wtag + (size_t)row * HH);
                float a = 0.0f;
#pragma unroll
                for (int it = 0; it < 8; ++it) {
                    float4 ww = wr[lane + 32 * it];
                    a += ww.x * hv[it].x + ww.y * hv[it].y + ww.z * hv[it].z + ww.w * hv[it].w;
                }
                a = wredsum(a);
                if (lane == 0) g_tagbuf[dir][i + 16][row] = a + btag[row];
            }
            __syncthreads();
            if (tid == 0) { __threadfence(); atomicAdd(&g_fTAG[dir][i], 1); }
        }
    }
}

// ---------------- final add + log_softmax ----------------------------------
__global__ void finalize(float* __restrict__ out) {
    int blk = blockIdx.x;          // b*SS + s
    int b = blk / SS, s = blk % SS;
    int lane = threadIdx.x;        // 32 threads
    int sf = (s * 16 + b) + 16;
    int sb = ((SS - 1 - s) * 16 + b) + 16;
    float v0 = g_tagbuf[0][sf][lane] + g_tagbuf[1][sb][lane];
    float v1 = g_tagbuf[0][sf][lane + 32] + g_tagbuf[1][sb][lane + 32];
    float m = fmaxf(v0, v1);
#pragma unroll
    for (int off = 16; off; off >>= 1) m = fmaxf(m, __shfl_xor_sync(0xffffffffu, m, off));
    float e = expf(v0 - m) + expf(v1 - m);
#pragma unroll
    for (int off = 16; off; off >>= 1) e += __shfl_xor_sync(0xffffffffu, e, off);
    float ls = m + logf(e);
    out[((size_t)b * SS + s) * TT + lane] = v0 - ls;
    out[((size_t)b * SS + s) * TT + lane + 32] = v1 - ls;
}

// ---------------- launch ----------------------------------------------------
extern "C" void kernel_launch(void* const* d_in, const int* in_sizes, int n_in,
                              void* d_out, int out_size) {
    const float* x = (const float*)d_in[0];
    const float* fWih0 = (const float*)d_in[1];
    const float* fWhh0 = (const float*)d_in[2];
    const float* fbih0 = (const float*)d_in[3];
    const float* fbhh0 = (const float*)d_in[4];
    const float* fWih1 = (const float*)d_in[5];
    const float* fWhh1 = (const float*)d_in[6];
    const float* fbih1 = (const float*)d_in[7];
    const float* fbhh1 = (const float*)d_in[8];
    const float* fWtag = (const float*)d_in[9];
    const float* fbtag = (const float*)d_in[10];
    const float* bWih0 = (const float*)d_in[11];
    const float* bWhh0 = (const float*)d_in[12];
    const float* bbih0 = (const float*)d_in[13];
    const float* bbhh0 = (const float*)d_in[14];
    const float* bWih1 = (const float*)d_in[15];
    const float* bWhh1 = (const float*)d_in[16];
    const float* bbih1 = (const float*)d_in[17];
    const float* bbhh1 = (const float*)d_in[18];
    const float* bWtag = (const float*)d_in[19];
    const float* bbtag = (const float*)d_in[20];

    zero_flags<<<16, 512>>>();
    xg_gemm<<<dim3(G4 / 64, G4 / 64, 2), 256>>>(x, fWih0, fbih0, fbhh0, bWih0, bbih0, bbhh0);
    lstm_seq<<<98, 512>>>(fWih0, fWhh0, fWih1, fWhh1, fbih1, fbhh1, fWtag, fbtag,
                          bWih0, bWhh0, bWih1, bWhh1, bbih1, bbhh1, bWtag, bbtag);
    finalize<<<BB * SS, 32>>>((float*)d_out);
}

// round 8
// speedup vs baseline: 1.0298x; 1.0278x over previous
#include <cuda_runtime.h>
#include <cstdint>

#define SS 256
#define BB 16
#define EE 512
#define HH 1024
#define TT 64
#define G4 4096
#define NSLOT 4096
#define DIN0 576

// ---------------- device scratch (static; no runtime allocation) ----------
__device__ float g_Xg[2][NSLOT][G4];        // layer0 gate x-part (+bih0+bhh0)
__device__ float g_a1[2][NSLOT][G4];        // layer1 gate input part (+biases)
__device__ float g_h0[2][NSLOT][HH];
__device__ float g_h1[2][NSLOT][HH];
__device__ float g_tagbuf[2][NSLOT + 16][TT];  // +16 rows of zeros at front
__device__ int   g_fH0[2][NSLOT];
__device__ int   g_fA1[2][NSLOT];
__device__ int   g_fH1[2][NSLOT];
__device__ int   g_fTAG[2][NSLOT];

// ---------------- helpers --------------------------------------------------
__device__ __forceinline__ int ld_acq(const int* p) {
    int v;
    asm volatile("ld.acquire.gpu.global.b32 %0, [%1];" : "=r"(v) : "l"(p));
    return v;
}
__device__ __forceinline__ void wait_ge(const int* p, int v) {
    while (ld_acq(p) < v) { __nanosleep(32); }
}
__device__ __forceinline__ float sigf(float x) { return 1.0f / (1.0f + expf(-x)); }
__device__ __forceinline__ float wredsum(float v) {
#pragma unroll
    for (int off = 16; off; off >>= 1) v += __shfl_xor_sync(0xffffffffu, v, off);
    return v;
}

// ---------------- flag / zero-init (graph-replay safe) ---------------------
__global__ void zero_flags() {
    int i = blockIdx.x * blockDim.x + threadIdx.x;
    if (i < 2 * NSLOT) {
        ((int*)g_fH0)[i] = 0;
        ((int*)g_fA1)[i] = 0;
        ((int*)g_fH1)[i] = 0;
        ((int*)g_fTAG)[i] = 0;
    }
    if (i < 2 * 16 * TT) {
        int d = i / (16 * TT);
        int r = i % (16 * TT);
        g_tagbuf[d][r / TT][r % TT] = 0.0f;
    }
}

// ---------------- Xg GEMM: (4096 slots) x (4096 rows) x (512) --------------
__global__ void __launch_bounds__(256) xg_gemm(
    const float* __restrict__ x,
    const float* __restrict__ Wf, const float* __restrict__ bihf, const float* __restrict__ bhhf,
    const float* __restrict__ Wb, const float* __restrict__ bihb, const float* __restrict__ bhhb) {
    int dir = blockIdx.z;
    const float* W   = dir ? Wb   : Wf;
    const float* bih = dir ? bihb : bihf;
    const float* bhh = dir ? bhhb : bhhf;
    int n0 = blockIdx.x * 64;
    int m0 = blockIdx.y * 64;

    __shared__ __align__(16) float As[32][72];
    __shared__ __align__(16) float Bs[32][72];

    int tid = threadIdx.x;
    int tm = tid >> 4, tn = tid & 15;
    float acc[4][4] = {};

    int th_row = tid >> 2;
    int th_c = (tid & 3) * 8;

    int mslot = m0 + th_row;
    int tt = mslot >> 4, bb = mslot & 15;
    int tsrc = dir ? (SS - 1 - tt) : tt;
    const float* arow = x + ((size_t)bb * SS + tsrc) * EE;
    const float* brow = W + (size_t)(n0 + th_row) * DIN0;

    for (int k0 = 0; k0 < EE; k0 += 32) {
#pragma unroll
        for (int u = 0; u < 8; ++u) {
            As[th_c + u][th_row] = arow[k0 + th_c + u];
            Bs[th_c + u][th_row] = brow[k0 + th_c + u];
        }
        __syncthreads();
#pragma unroll
        for (int kk = 0; kk < 32; ++kk) {
            float av[4], bv[4];
            *(float4*)av = *(const float4*)&As[kk][tm * 4];
            *(float4*)bv = *(const float4*)&Bs[kk][tn * 4];
#pragma unroll
            for (int ii = 0; ii < 4; ++ii)
#pragma unroll
                for (int jj = 0; jj < 4; ++jj) acc[ii][jj] += av[ii] * bv[jj];
        }
        __syncthreads();
    }
#pragma unroll
    for (int ii = 0; ii < 4; ++ii) {
        int m = m0 + tm * 4 + ii;
#pragma unroll
        for (int jj = 0; jj < 4; ++jj) {
            int n = n0 + tn * 4 + jj;
            g_Xg[dir][m][n] = acc[ii][jj] + bih[n] + bhh[n];
        }
    }
}

// ---------------- persistent pipelined sequential kernel -------------------
// 98 blocks: per dir 49: [0..15] E0, [16..31] E1A, [32..47] E1B, [48] TAG.
__global__ void __launch_bounds__(512, 1) lstm_seq(
    const float* __restrict__ fWih0, const float* __restrict__ fWhh0,
    const float* __restrict__ fWih1, const float* __restrict__ fWhh1,
    const float* __restrict__ fbih1, const float* __restrict__ fbhh1,
    const float* __restrict__ fWtag, const float* __restrict__ fbtag,
    const float* __restrict__ bWih0, const float* __restrict__ bWhh0,
    const float* __restrict__ bWih1, const float* __restrict__ bWhh1,
    const float* __restrict__ bbih1, const float* __restrict__ bbhh1,
    const float* __restrict__ bWtag, const float* __restrict__ bbtag) {
    int dir = blockIdx.x / 49;
    int role = blockIdx.x % 49;
    const float* Wih0 = dir ? bWih0 : fWih0;
    const float* Whh0 = dir ? bWhh0 : fWhh0;
    const float* Wih1 = dir ? bWih1 : fWih1;
    const float* Whh1 = dir ? bWhh1 : fWhh1;
    const float* bih1 = dir ? bbih1 : fbih1;
    const float* bhh1 = dir ? bbhh1 : fbhh1;
    const float* Wtag = dir ? bWtag : fWtag;
    const float* btag = dir ? bbtag : fbtag;

    int tid = threadIdx.x;
    int w = tid >> 5, lane = tid & 31;

    __shared__ __align__(16) float sh_h[HH];
    __shared__ float sh_tag[TT];
    __shared__ float sh_acc[16][16];
    __shared__ float c_sh[64];

    if (role < 16) {
        // ------- E0: layer-0 recurrence (Whh0 + prev-tag cols of Wih0) -----
        int hbase = role * 64;
        if (tid < 64) c_sh[tid] = 0.0f;
        for (int i = 0; i < NSLOT; ++i) {
            if (tid == 0) {
                if (i > 0) wait_ge(&g_fH0[dir][i - 1], 16);
                if (i >= 16) wait_ge(&g_fTAG[dir][i - 16], 1);
            }
            __syncthreads();
            if (i > 0) {
                for (int q = tid; q < HH; q += 512) sh_h[q] = g_h0[dir][i - 1][q];
            } else {
                for (int q = tid; q < HH; q += 512) sh_h[q] = 0.0f;
            }
            if (tid < 64) sh_tag[tid] = g_tagbuf[dir][i][tid];
            __syncthreads();

            float4 hv[8];
            const float4* shf = (const float4*)sh_h;
#pragma unroll
            for (int it = 0; it < 8; ++it) hv[it] = shf[lane + 32 * it];
            float tp0 = sh_tag[lane * 2], tp1 = sh_tag[lane * 2 + 1];

            for (int r = 0; r < 16; ++r) {
                int u = r >> 2, gsel = r & 3;
                int row = gsel * 1024 + hbase + w * 4 + u;
                const float4* wr = (const float4*)(Whh0 + (size_t)row * HH);
                float a = 0.0f;
#pragma unroll
                for (int it = 0; it < 8; ++it) {
                    float4 ww = wr[lane + 32 * it];
                    a += ww.x * hv[it].x + ww.y * hv[it].y + ww.z * hv[it].z + ww.w * hv[it].w;
                }
                float2 wp = *(const float2*)(Wih0 + (size_t)row * DIN0 + 512 + lane * 2);
                a += wp.x * tp0 + wp.y * tp1;
                a = wredsum(a);
                if (lane == 0) sh_acc[w][r] = a + g_Xg[dir][i][row];
            }
            __syncwarp();
            if (lane < 4) {
                int lj = w * 4 + lane;
                float gi = sh_acc[w][lane * 4 + 0];
                float gf = sh_acc[w][lane * 4 + 1];
                float gg = sh_acc[w][lane * 4 + 2];
                float go = sh_acc[w][lane * 4 + 3];
                float c = sigf(gf) * c_sh[lj] + sigf(gi) * tanhf(gg);
                float h = sigf(go) * tanhf(c);
                c_sh[lj] = c;
                g_h0[dir][i][hbase + lj] = h;
            }
            __syncthreads();
            if (tid == 0) { __threadfence(); atomicAdd(&g_fH0[dir][i], 1); }
        }
    } else if (role < 32) {
        // ------- E1A: a1 = Wih1 . h0 + biases ------------------------------
        int rbase = (role - 16) * 256;
        for (int i = 0; i < NSLOT; ++i) {
            if (tid == 0) wait_ge(&g_fH0[dir][i], 16);
            __syncthreads();
            for (int q = tid; q < HH; q += 512) sh_h[q] = g_h0[dir][i][q];
            __syncthreads();
            float4 hv[8];
            const float4* shf = (const float4*)sh_h;
#pragma unroll
            for (int it = 0; it < 8; ++it) hv[it] = shf[lane + 32 * it];
            for (int r = 0; r < 16; ++r) {
                int row = rbase + w * 16 + r;
                const float4* wr = (const float4*)(Wih1 + (size_t)row * HH);
                float a = 0.0f;
#pragma unroll
                for (int it = 0; it < 8; ++it) {
                    float4 ww = wr[lane + 32 * it];
                    a += ww.x * hv[it].x + ww.y * hv[it].y + ww.z * hv[it].z + ww.w * hv[it].w;
                }
                a = wredsum(a);
                if (lane == 0) g_a1[dir][i][row] = a + bih1[row] + bhh1[row];
            }
            __syncthreads();
            if (tid == 0) { __threadfence(); atomicAdd(&g_fA1[dir][i], 1); }
        }
    } else if (role < 48) {
        // ------- E1B: layer-1 recurrence (Whh1) ----------------------------
        int hbase = (role - 32) * 64;
        if (tid < 64) c_sh[tid] = 0.0f;
        for (int i = 0; i < NSLOT; ++i) {
            if (tid == 0) {
                wait_ge(&g_fA1[dir][i], 16);
                if (i > 0) wait_ge(&g_fH1[dir][i - 1], 16);
            }
            __syncthreads();
            if (i > 0) {
                for (int q = tid; q < HH; q += 512) sh_h[q] = g_h1[dir][i - 1][q];
            } else {
                for (int q = tid; q < HH; q += 512) sh_h[q] = 0.0f;
            }
            __syncthreads();
            float4 hv[8];
            const float4* shf = (const float4*)sh_h;
#pragma unroll
            for (int it = 0; it < 8; ++it) hv[it] = shf[lane + 32 * it];
            for (int r = 0; r < 16; ++r) {
                int u = r >> 2, gsel = r & 3;
                int row = gsel * 1024 + hbase + w * 4 + u;
                const float4* wr = (const float4*)(Whh1 + (size_t)row * HH);
                float a = 0.0f;
#pragma unroll
                for (int it = 0; it < 8; ++it) {
                    float4 ww = wr[lane + 32 * it];
                    a += ww.x * hv[it].x + ww.y * hv[it].y + ww.z * hv[it].z + ww.w * hv[it].w;
                }
                a = wredsum(a);
                if (lane == 0) sh_acc[w][r] = a + g_a1[dir][i][row];
            }
            __syncwarp();
            if (lane < 4) {
                int lj = w * 4 + lane;
                float gi = sh_acc[w][lane * 4 + 0];
                float gf = sh_acc[w][lane * 4 + 1];
                float gg = sh_acc[w][lane * 4 + 2];
                float go = sh_acc[w][lane * 4 + 3];
                float c = sigf(gf) * c_sh[lj] + sigf(gi) * tanhf(gg);
                float h = sigf(go) * tanhf(c);
                c_sh[lj] = c;
                g_h1[dir][i][hbase + lj] = h;
            }
            __syncthreads();
            if (tid == 0) { __threadfence(); atomicAdd(&g_fH1[dir][i], 1); }
        }
    } else {
        // ------- TAG: out = Wtag . h1 + btag -------------------------------
        for (int i = 0; i < NSLOT; ++i) {
            if (tid == 0) wait_ge(&g_fH1[dir][i], 16);
            __syncthreads();
            for (int q = tid; q < HH; q += 512) sh_h[q] = g_h1[dir][i][q];
            __syncthreads();
            float4 hv[8];
            const float4* shf = (const float4*)sh_h;
#pragma unroll
            for (int it = 0; it < 8; ++it) hv[it] = shf[lane + 32 * it];
            for (int r = 0; r < 4; ++r) {
                int row = w * 4 + r;
                const float4* wr = (const float4*)(Wtag + (size_t)row * HH);
                float a = 0.0f;
#pragma unroll
                for (int it = 0; it < 8; ++it) {
                    float4 ww = wr[lane + 32 * it];
                    a += ww.x * hv[it].x + ww.y * hv[it].y + ww.z * hv[it].z + ww.w * hv[it].w;
                }
                a = wredsum(a);
                if (lane == 0) g_tagbuf[dir][i + 16][row] = a + btag[row];
            }
            __syncthreads();
            if (tid == 0) { __threadfence(); atomicAdd(&g_fTAG[dir][i], 1); }
        }
    }
}

// ---------------- final add + log_softmax ----------------------------------
__global__ void finalize(float* __restrict__ out) {
    int blk = blockIdx.x;          // b*SS + s
    int b = blk / SS, s = blk % SS;
    int lane = threadIdx.x;        // 32 threads
    int sf = (s * 16 + b) + 16;
    int sb = ((SS - 1 - s) * 16 + b) + 16;
    float v0 = g_tagbuf[0][sf][lane] + g_tagbuf[1][sb][lane];
    float v1 = g_tagbuf[0][sf][lane + 32] + g_tagbuf[1][sb][lane + 32];
    float m = fmaxf(v0, v1);
#pragma unroll
    for (int off = 16; off; off >>= 1) m = fmaxf(m, __shfl_xor_sync(0xffffffffu, m, off));
    float e = expf(v0 - m) + expf(v1 - m);
#pragma unroll
    for (int off = 16; off; off >>= 1) e += __shfl_xor_sync(0xffffffffu, e, off);
    float ls = m + logf(e);
    out[((size_t)b * SS + s) * TT + lane] = v0 - ls;
    out[((size_t)b * SS + s) * TT + lane + 32] = v1 - ls;
}

// ---------------- launch ----------------------------------------------------
extern "C" void kernel_launch(void* const* d_in, const int* in_sizes, int n_in,
                              void* d_out, int out_size) {
    const float* x = (const float*)d_in[0];
    const float* fWih0 = (const float*)d_in[1];
    const float* fWhh0 = (const float*)d_in[2];
    const float* fbih0 = (const float*)d_in[3];
    const float* fbhh0 = (const float*)d_in[4];
    const float* fWih1 = (const float*)d_in[5];
    const float* fWhh1 = (const float*)d_in[6];
    const float* fbih1 = (const float*)d_in[7];
    const float* fbhh1 = (const float*)d_in[8];
    const float* fWtag = (const float*)d_in[9];
    const float* fbtag = (const float*)d_in[10];
    const float* bWih0 = (const float*)d_in[11];
    const float* bWhh0 = (const float*)d_in[12];
    const float* bbih0 = (const float*)d_in[13];
    const float* bbhh0 = (const float*)d_in[14];
    const float* bWih1 = (const float*)d_in[15];
    const float* bWhh1 = (const float*)d_in[16];
    const float* bbih1 = (const float*)d_in[17];
    const float* bbhh1 = (const float*)d_in[18];
    const float* bWtag = (const float*)d_in[19];
    const float* bbtag = (const float*)d_in[20];

    zero_flags<<<16, 512>>>();
    xg_gemm<<<dim3(G4 / 64, G4 / 64, 2), 256>>>(x, fWih0, fbih0, fbhh0, bWih0, bbih0, bbhh0);
    lstm_seq<<<98, 512>>>(fWih0, fWhh0, fWih1, fWhh1, fbih1, fbhh1, fWtag, fbtag,
                          bWih0, bWhh0, bWih1, bWhh1, bbih1, bbhh1, bWtag, bbtag);
    finalize<<<BB * SS, 32>>>((float*)d_out);
}

// round 9
// speedup vs baseline: 1.0302x; 1.0004x over previous
#include <cuda_runtime.h>
#include <cstdint>

#define SS 256
#define BB 16
#define EE 512
#define HH 1024
#define TT 64
#define G4 4096
#define NSLOT 4096
#define DIN0 576

// ---------------- device scratch (static; no runtime allocation) ----------
__device__ float g_Xg[2][NSLOT][G4];        // layer0 gate x-part (+bih0+bhh0)
__device__ float g_a1[2][NSLOT][G4];        // layer1 gate input part (+biases)
__device__ float g_h0[2][NSLOT][HH];
__device__ float g_h1[2][NSLOT][HH];
__device__ float g_tagbuf[2][NSLOT + 16][TT];  // +16 rows of zeros at front
__device__ int   g_fH0[2][NSLOT];
__device__ int   g_fA1[2][NSLOT];
__device__ int   g_fH1[2][NSLOT];
__device__ int   g_fTAG[2][NSLOT];

// ---------------- helpers --------------------------------------------------
__device__ __forceinline__ int ld_acq(const int* p) {
    int v;
    asm volatile("ld.acquire.gpu.global.b32 %0, [%1];" : "=r"(v) : "l"(p));
    return v;
}
__device__ __forceinline__ void wait_ge(const int* p, int v) {
    while (ld_acq(p) < v) { __nanosleep(32); }
}
__device__ __forceinline__ float sigf(float x) { return 1.0f / (1.0f + expf(-x)); }
__device__ __forceinline__ float wredsum(float v) {
#pragma unroll
    for (int off = 16; off; off >>= 1) v += __shfl_xor_sync(0xffffffffu, v, off);
    return v;
}

// ---------------- flag / zero-init (graph-replay safe) ---------------------
__global__ void zero_flags() {
    int i = blockIdx.x * blockDim.x + threadIdx.x;
    if (i < 2 * NSLOT) {
        ((int*)g_fH0)[i] = 0;
        ((int*)g_fA1)[i] = 0;
        ((int*)g_fH1)[i] = 0;
        ((int*)g_fTAG)[i] = 0;
    }
    if (i < 2 * 16 * TT) {
        int d = i / (16 * TT);
        int r = i % (16 * TT);
        g_tagbuf[d][r / TT][r % TT] = 0.0f;
    }
}

// ---------------- Xg GEMM: (4096 slots) x (4096 rows) x (512) --------------
__global__ void __launch_bounds__(256) xg_gemm(
    const float* __restrict__ x,
    const float* __restrict__ Wf, const float* __restrict__ bihf, const float* __restrict__ bhhf,
    const float* __restrict__ Wb, const float* __restrict__ bihb, const float* __restrict__ bhhb) {
    int dir = blockIdx.z;
    const float* W   = dir ? Wb   : Wf;
    const float* bih = dir ? bihb : bihf;
    const float* bhh = dir ? bhhb : bhhf;
    int n0 = blockIdx.x * 64;
    int m0 = blockIdx.y * 64;

    __shared__ __align__(16) float As[32][72];
    __shared__ __align__(16) float Bs[32][72];

    int tid = threadIdx.x;
    int tm = tid >> 4, tn = tid & 15;
    float acc[4][4] = {};

    int th_row = tid >> 2;
    int th_c = (tid & 3) * 8;

    int mslot = m0 + th_row;
    int tt = mslot >> 4, bb = mslot & 15;
    int tsrc = dir ? (SS - 1 - tt) : tt;
    const float* arow = x + ((size_t)bb * SS + tsrc) * EE;
    const float* brow = W + (size_t)(n0 + th_row) * DIN0;

    for (int k0 = 0; k0 < EE; k0 += 32) {
#pragma unroll
        for (int u = 0; u < 8; ++u) {
            As[th_c + u][th_row] = arow[k0 + th_c + u];
            Bs[th_c + u][th_row] = brow[k0 + th_c + u];
        }
        __syncthreads();
#pragma unroll
        for (int kk = 0; kk < 32; ++kk) {
            float av[4], bv[4];
            *(float4*)av = *(const float4*)&As[kk][tm * 4];
            *(float4*)bv = *(const float4*)&Bs[kk][tn * 4];
#pragma unroll
            for (int ii = 0; ii < 4; ++ii)
#pragma unroll
                for (int jj = 0; jj < 4; ++jj) acc[ii][jj] += av[ii] * bv[jj];
        }
        __syncthreads();
    }
#pragma unroll
    for (int ii = 0; ii < 4; ++ii) {
        int m = m0 + tm * 4 + ii;
#pragma unroll
        for (int jj = 0; jj < 4; ++jj) {
            int n = n0 + tn * 4 + jj;
            g_Xg[dir][m][n] = acc[ii][jj] + bih[n] + bhh[n];
        }
    }
}

// ---------------- persistent pipelined sequential kernel -------------------
// 98 blocks: per dir 49: [0..15] E0, [16..31] E1A, [32..47] E1B, [48] TAG.
__global__ void __launch_bounds__(512, 1) lstm_seq(
    const float* __restrict__ fWih0, const float* __restrict__ fWhh0,
    const float* __restrict__ fWih1, const float* __restrict__ fWhh1,
    const float* __restrict__ fbih1, const float* __restrict__ fbhh1,
    const float* __restrict__ fWtag, const float* __restrict__ fbtag,
    const float* __restrict__ bWih0, const float* __restrict__ bWhh0,
    const float* __restrict__ bWih1, const float* __restrict__ bWhh1,
    const float* __restrict__ bbih1, const float* __restrict__ bbhh1,
    const float* __restrict__ bWtag, const float* __restrict__ bbtag) {
    int dir = blockIdx.x / 49;
    int role = blockIdx.x % 49;
    const float* Wih0 = dir ? bWih0 : fWih0;
    const float* Whh0 = dir ? bWhh0 : fWhh0;
    const float* Wih1 = dir ? bWih1 : fWih1;
    const float* Whh1 = dir ? bWhh1 : fWhh1;
    const float* bih1 = dir ? bbih1 : fbih1;
    const float* bhh1 = dir ? bbhh1 : fbhh1;
    const float* Wtag = dir ? bWtag : fWtag;
    const float* btag = dir ? bbtag : fbtag;

    int tid = threadIdx.x;
    int w = tid >> 5, lane = tid & 31;

    __shared__ __align__(16) float sh_h[HH];
    __shared__ float sh_tag[TT];
    __shared__ float sh_acc[16][16];
    __shared__ float c_sh[64];

    if (role < 16) {
        // ------- E0: layer-0 recurrence (Whh0 + prev-tag cols of Wih0) -----
        int hbase = role * 64;
        if (tid < 64) c_sh[tid] = 0.0f;
        for (int i = 0; i < NSLOT; ++i) {
            if (tid == 0) {
                if (i > 0) wait_ge(&g_fH0[dir][i - 1], 16);
                if (i >= 16) wait_ge(&g_fTAG[dir][i - 16], 1);
            }
            __syncthreads();
            if (i > 0) {
                for (int q = tid; q < HH; q += 512) sh_h[q] = g_h0[dir][i - 1][q];
            } else {
                for (int q = tid; q < HH; q += 512) sh_h[q] = 0.0f;
            }
            if (tid < 64) sh_tag[tid] = g_tagbuf[dir][i][tid];
            __syncthreads();

            float4 hv[8];
            const float4* shf = (const float4*)sh_h;
#pragma unroll
            for (int it = 0; it < 8; ++it) hv[it] = shf[lane + 32 * it];
            float tp0 = sh_tag[lane * 2], tp1 = sh_tag[lane * 2 + 1];

            for (int r = 0; r < 16; ++r) {
                int u = r >> 2, gsel = r & 3;
                int row = gsel * 1024 + hbase + w * 4 + u;
                const float4* wr = (const float4*)(Whh0 + (size_t)row * HH);
                float a = 0.0f;
#pragma unroll
                for (int it = 0; it < 8; ++it) {
                    float4 ww = wr[lane + 32 * it];
                    a += ww.x * hv[it].x + ww.y * hv[it].y + ww.z * hv[it].z + ww.w * hv[it].w;
                }
                float2 wp = *(const float2*)(Wih0 + (size_t)row * DIN0 + 512 + lane * 2);
                a += wp.x * tp0 + wp.y * tp1;
                a = wredsum(a);
                if (lane == 0) sh_acc[w][r] = a + g_Xg[dir][i][row];
            }
            __syncwarp();
            if (lane < 4) {
                int lj = w * 4 + lane;
                float gi = sh_acc[w][lane * 4 + 0];
                float gf = sh_acc[w][lane * 4 + 1];
                float gg = sh_acc[w][lane * 4 + 2];
                float go = sh_acc[w][lane * 4 + 3];
                float c = sigf(gf) * c_sh[lj] + sigf(gi) * tanhf(gg);
                float h = sigf(go) * tanhf(c);
                c_sh[lj] = c;
                g_h0[dir][i][hbase + lj] = h;
            }
            __syncthreads();
            if (tid == 0) { __threadfence(); atomicAdd(&g_fH0[dir][i], 1); }
        }
    } else if (role < 32) {
        // ------- E1A: a1 = Wih1 . h0 + biases ------------------------------
        int rbase = (role - 16) * 256;
        for (int i = 0; i < NSLOT; ++i) {
            if (tid == 0) wait_ge(&g_fH0[dir][i], 16);
            __syncthreads();
            for (int q = tid; q < HH; q += 512) sh_h[q] = g_h0[dir][i][q];
            __syncthreads();
            float4 hv[8];
            const float4* shf = (const float4*)sh_h;
#pragma unroll
            for (int it = 0; it < 8; ++it) hv[it] = shf[lane + 32 * it];
            for (int r = 0; r < 16; ++r) {
                int row = rbase + w * 16 + r;
                const float4* wr = (const float4*)(Wih1 + (size_t)row * HH);
                float a = 0.0f;
#pragma unroll
                for (int it = 0; it < 8; ++it) {
                    float4 ww = wr[lane + 32 * it];
                    a += ww.x * hv[it].x + ww.y * hv[it].y + ww.z * hv[it].z + ww.w * hv[it].w;
                }
                a = wredsum(a);
                if (lane == 0) g_a1[dir][i][row] = a + bih1[row] + bhh1[row];
            }
            __syncthreads();
            if (tid == 0) { __threadfence(); atomicAdd(&g_fA1[dir][i], 1); }
        }
    } else if (role < 48) {
        // ------- E1B: layer-1 recurrence (Whh1) ----------------------------
        int hbase = (role - 32) * 64;
        if (tid < 64) c_sh[tid] = 0.0f;
        for (int i = 0; i < NSLOT; ++i) {
            if (tid == 0) {
                wait_ge(&g_fA1[dir][i], 16);
                if (i > 0) wait_ge(&g_fH1[dir][i - 1], 16);
            }
            __syncthreads();
            if (i > 0) {
                for (int q = tid; q < HH; q += 512) sh_h[q] = g_h1[dir][i - 1][q];
            } else {
                for (int q = tid; q < HH; q += 512) sh_h[q] = 0.0f;
            }
            __syncthreads();
            float4 hv[8];
            const float4* shf = (const float4*)sh_h;
#pragma unroll
            for (int it = 0; it < 8; ++it) hv[it] = shf[lane + 32 * it];
            for (int r = 0; r < 16; ++r) {
                int u = r >> 2, gsel = r & 3;
                int row = gsel * 1024 + hbase + w * 4 + u;
                const float4* wr = (const float4*)(Whh1 + (size_t)row * HH);
                float a = 0.0f;
#pragma unroll
                for (int it = 0; it < 8; ++it) {
                    float4 ww = wr[lane + 32 * it];
                    a += ww.x * hv[it].x + ww.y * hv[it].y + ww.z * hv[it].z + ww.w * hv[it].w;
                }
                a = wredsum(a);
                if (lane == 0) sh_acc[w][r] = a + g_a1[dir][i][row];
            }
            __syncwarp();
            if (lane < 4) {
                int lj = w * 4 + lane;
                float gi = sh_acc[w][lane * 4 + 0];
                float gf = sh_acc[w][lane * 4 + 1];
                float gg = sh_acc[w][lane * 4 + 2];
                float go = sh_acc[w][lane * 4 + 3];
                float c = sigf(gf) * c_sh[lj] + sigf(gi) * tanhf(gg);
                float h = sigf(go) * tanhf(c);
                c_sh[lj] = c;
                g_h1[dir][i][hbase + lj] = h;
            }
            __syncthreads();
            if (tid == 0) { __threadfence(); atomicAdd(&g_fH1[dir][i], 1); }
        }
    } else {
        // ------- TAG: out = Wtag . h1 + btag -------------------------------
        for (int i = 0; i < NSLOT; ++i) {
            if (tid == 0) wait_ge(&g_fH1[dir][i], 16);
            __syncthreads();
            for (int q = tid; q < HH; q += 512) sh_h[q] = g_h1[dir][i][q];
            __syncthreads();
            float4 hv[8];
            const float4* shf = (const float4*)sh_h;
#pragma unroll
            for (int it = 0; it < 8; ++it) hv[it] = shf[lane + 32 * it];
            for (int r = 0; r < 4; ++r) {
                int row = w * 4 + r;
                const float4* wr = (const float4*)(Wtag + (size_t)row * HH);
                float a = 0.0f;
#pragma unroll
                for (int it = 0; it < 8; ++it) {
                    float4 ww = wr[lane + 32 * it];
                    a += ww.x * hv[it].x + ww.y * hv[it].y + ww.z * hv[it].z + ww.w * hv[it].w;
                }
                a = wredsum(a);
                if (lane == 0) g_tagbuf[dir][i + 16][row] = a + btag[row];
            }
            __syncthreads();
            if (tid == 0) { __threadfence(); atomicAdd(&g_fTAG[dir][i], 1); }
        }
    }
}

// ---------------- final add + log_softmax ----------------------------------
__global__ void finalize(float* __restrict__ out) {
    int blk = blockIdx.x;          // b*SS + s
    int b = blk / SS, s = blk % SS;
    int lane = threadIdx.x;        // 32 threads
    int sf = (s * 16 + b) + 16;
    int sb = ((SS - 1 - s) * 16 + b) + 16;
    float v0 = g_tagbuf[0][sf][lane] + g_tagbuf[1][sb][lane];
    float v1 = g_tagbuf[0][sf][lane + 32] + g_tagbuf[1][sb][lane + 32];
    float m = fmaxf(v0, v1);
#pragma unroll
    for (int off = 16; off; off >>= 1) m = fmaxf(m, __shfl_xor_sync(0xffffffffu, m, off));
    float e = expf(v0 - m) + expf(v1 - m);
#pragma unroll
    for (int off = 16; off; off >>= 1) e += __shfl_xor_sync(0xffffffffu, e, off);
    float ls = m + logf(e);
    out[((size_t)b * SS + s) * TT + lane] = v0 - ls;
    out[((size_t)b * SS + s) * TT + lane + 32] = v1 - ls;
}

// ---------------- launch ----------------------------------------------------
extern "C" void kernel_launch(void* const* d_in, const int* in_sizes, int n_in,
                              void* d_out, int out_size) {
    const float* x = (const float*)d_in[0];
    const float* fWih0 = (const float*)d_in[1];
    const float* fWhh0 = (const float*)d_in[2];
    const float* fbih0 = (const float*)d_in[3];
    const float* fbhh0 = (const float*)d_in[4];
    const float* fWih1 = (const float*)d_in[5];
    const float* fWhh1 = (const float*)d_in[6];
    const float* fbih1 = (const float*)d_in[7];
    const float* fbhh1 = (const float*)d_in[8];
    const float* fWtag = (const float*)d_in[9];
    const float* fbtag = (const float*)d_in[10];
    const float* bWih0 = (const float*)d_in[11];
    const float* bWhh0 = (const float*)d_in[12];
    const float* bbih0 = (const float*)d_in[13];
    const float* bbhh0 = (const float*)d_in[14];
    const float* bWih1 = (const float*)d_in[15];
    const float* bWhh1 = (const float*)d_in[16];
    const float* bbih1 = (const float*)d_in[17];
    const float* bbhh1 = (const float*)d_in[18];
    const float* bWtag = (const float*)d_in[19];
    const float* bbtag = (const float*)d_in[20];

    zero_flags<<<16, 512>>>();
    xg_gemm<<<dim3(G4 / 64, G4 / 64, 2), 256>>>(x, fWih0, fbih0, fbhh0, bWih0, bbih0, bbhh0);
    lstm_seq<<<98, 512>>>(fWih0, fWhh0, fWih1, fWhh1, fbih1, fbhh1, fWtag, fbtag,
                          bWih0, bWhh0, bWih1, bWhh1, bbih1, bbhh1, bWtag, bbtag);
    finalize<<<BB * SS, 32>>>((float*)d_out);
}